// round 4
// baseline (speedup 1.0000x reference)
#include <cuda_runtime.h>
#include <math.h>

#define NN   256
#define CZ   128
#define H    4
#define DH   32
#define NPOS (NN*NN)

// Scratch (device globals: allocation-free rule).
// Referenced ONLY from device code.
__device__ __align__(16) float g_xn[NPOS*CZ];
__device__ __align__(16) float g_q [NPOS*CZ];
__device__ __align__(16) float g_k [NPOS*CZ];
__device__ __align__(16) float g_v [NPOS*CZ];
__device__ __align__(16) float g_g [NPOS*CZ];
__device__ __align__(16) float g_o [NPOS*CZ];
__device__ __align__(16) float g_tri[H*NPOS];

// ---- packed f32x2 helpers (sm_100+: FFMA2 only reachable via explicit PTX) ----
__device__ __forceinline__ void ffma2(float2& d, const float2& a, const float2& b) {
    asm("fma.rn.f32x2 %0, %1, %2, %0;"
        : "+l"(reinterpret_cast<unsigned long long&>(d))
        : "l"(reinterpret_cast<const unsigned long long&>(a)),
          "l"(reinterpret_cast<const unsigned long long&>(b)));
}
__device__ __forceinline__ void fmul2(float2& d, const float2& a, const float2& b) {
    asm("mul.rn.f32x2 %0, %1, %2;"
        : "=l"(reinterpret_cast<unsigned long long&>(d))
        : "l"(reinterpret_cast<const unsigned long long&>(a)),
          "l"(reinterpret_cast<const unsigned long long&>(b)));
}
__device__ __forceinline__ float2 pack2(float x) {
    float2 r;
    asm("mov.b64 %0, {%1, %1};"
        : "=l"(reinterpret_cast<unsigned long long&>(r)) : "f"(x));
    return r;
}

// ---------------------------------------------------------------------------
// K1: LayerNorm over c_z (warp per position) + fused triangle bias
// ---------------------------------------------------------------------------
__global__ __launch_bounds__(256) void k_ln(
    const float* __restrict__ x,
    const float* __restrict__ ln_g,
    const float* __restrict__ ln_b,
    const float* __restrict__ w_tri)
{
    int warp = threadIdx.x >> 5;
    int lane = threadIdx.x & 31;
    int pos  = blockIdx.x * 8 + warp;          // grid = NPOS/8

    float4 v = *(const float4*)(x + (size_t)pos*CZ + lane*4);
    float s  = v.x + v.y + v.z + v.w;
    float ss = v.x*v.x + v.y*v.y + v.z*v.z + v.w*v.w;
    #pragma unroll
    for (int off = 16; off; off >>= 1) {
        s  += __shfl_xor_sync(0xffffffffu, s,  off);
        ss += __shfl_xor_sync(0xffffffffu, ss, off);
    }
    float mu  = s * (1.0f/CZ);
    float var = ss * (1.0f/CZ) - mu*mu;
    float rs  = rsqrtf(var + 1e-5f);

    float4 gg = *(const float4*)(ln_g + lane*4);
    float4 bb = *(const float4*)(ln_b + lane*4);
    float4 y;
    y.x = (v.x - mu)*rs*gg.x + bb.x;
    y.y = (v.y - mu)*rs*gg.y + bb.y;
    y.z = (v.z - mu)*rs*gg.z + bb.z;
    y.w = (v.w - mu)*rs*gg.w + bb.w;
    *(float4*)(g_xn + (size_t)pos*CZ + lane*4) = y;

    #pragma unroll
    for (int h = 0; h < H; h++) {
        float4 w = *(const float4*)(w_tri + h*CZ + lane*4);
        float d = y.x*w.x + y.y*w.y + y.z*w.z + y.w*w.w;
        #pragma unroll
        for (int off = 16; off; off >>= 1)
            d += __shfl_xor_sync(0xffffffffu, d, off);
        if (lane == 0) g_tri[h*NPOS + pos] = d;
    }
}

// ---------------------------------------------------------------------------
// K2: generic GEMM  y[pos][o] = act( sum_c A[pos][c] * W[o][c] + bias )
//     128x128 block tile, 8x8 per thread, packed f32x2 inner loop.
//     sel: 0..3 -> A=g_xn, out=g_{q,k,v,g} (sel 3: sigmoid(y+bias))
//     sel: 4    -> A=g_o,  out=extout (y+bias)
// ---------------------------------------------------------------------------
__global__ __launch_bounds__(256) void k_gemm(
    int sel,
    const float* __restrict__ W,
    const float* __restrict__ bias,
    float* __restrict__ extout)
{
    const float* A = (sel == 4) ? g_o : g_xn;
    float* out = (sel==0) ? g_q : (sel==1) ? g_k : (sel==2) ? g_v
               : (sel==3) ? g_g : extout;

    __shared__ float a_s[16][128];   // [k][pos]
    __shared__ float w_s[16][128];   // [k][out]

    int p0 = blockIdx.x * 128;
    int t  = threadIdx.x;
    int tx = t & 15;        // 16 groups -> 8 outputs each
    int ty = t >> 4;        // 16 groups -> 8 positions each

    float2 acc[8][4];
    #pragma unroll
    for (int m = 0; m < 8; m++)
        #pragma unroll
        for (int n = 0; n < 4; n++) acc[m][n] = make_float2(0.f, 0.f);

    float4 pa[2], pw[2];
    #pragma unroll
    for (int i = 0; i < 2; i++) {
        int idx = t + i*256;                  // 0..511
        int p = idx >> 2, f = idx & 3;
        pa[i] = *(const float4*)(A + (size_t)(p0+p)*CZ + f*4);
        pw[i] = *(const float4*)(W + (size_t)p*CZ + f*4);
    }

    for (int c0 = 0; c0 < CZ; c0 += 16) {
        #pragma unroll
        for (int i = 0; i < 2; i++) {
            int idx = t + i*256;
            int p = idx >> 2, f = idx & 3;
            a_s[f*4+0][p] = pa[i].x; a_s[f*4+1][p] = pa[i].y;
            a_s[f*4+2][p] = pa[i].z; a_s[f*4+3][p] = pa[i].w;
            w_s[f*4+0][p] = pw[i].x; w_s[f*4+1][p] = pw[i].y;
            w_s[f*4+2][p] = pw[i].z; w_s[f*4+3][p] = pw[i].w;
        }
        __syncthreads();

        if (c0 + 16 < CZ) {
            #pragma unroll
            for (int i = 0; i < 2; i++) {
                int idx = t + i*256;
                int p = idx >> 2, f = idx & 3;
                pa[i] = *(const float4*)(A + (size_t)(p0+p)*CZ + c0 + 16 + f*4);
                pw[i] = *(const float4*)(W + (size_t)p*CZ + c0 + 16 + f*4);
            }
        }

        #pragma unroll
        for (int kk = 0; kk < 16; kk++) {
            float4 a0 = *(const float4*)&a_s[kk][ty*8];
            float4 a1 = *(const float4*)&a_s[kk][ty*8+4];
            float4 b0 = *(const float4*)&w_s[kk][tx*8];
            float4 b1 = *(const float4*)&w_s[kk][tx*8+4];
            float  a[8] = {a0.x,a0.y,a0.z,a0.w,a1.x,a1.y,a1.z,a1.w};
            float2 b[4] = {{b0.x,b0.y},{b0.z,b0.w},{b1.x,b1.y},{b1.z,b1.w}};
            #pragma unroll
            for (int m = 0; m < 8; m++) {
                float2 am = pack2(a[m]);
                #pragma unroll
                for (int n = 0; n < 4; n++)
                    ffma2(acc[m][n], am, b[n]);
            }
        }
        __syncthreads();
    }

    #pragma unroll
    for (int m = 0; m < 8; m++) {
        int pos = p0 + ty*8 + m;
        #pragma unroll
        for (int n2 = 0; n2 < 2; n2++) {
            int ob = tx*8 + n2*4;
            float4 v;
            v.x = acc[m][n2*2+0].x; v.y = acc[m][n2*2+0].y;
            v.z = acc[m][n2*2+1].x; v.w = acc[m][n2*2+1].y;
            if (sel == 3) {
                v.x = 1.0f/(1.0f + __expf(-(v.x + bias[ob+0])));
                v.y = 1.0f/(1.0f + __expf(-(v.y + bias[ob+1])));
                v.z = 1.0f/(1.0f + __expf(-(v.z + bias[ob+2])));
                v.w = 1.0f/(1.0f + __expf(-(v.w + bias[ob+3])));
            } else if (sel == 4) {
                v.x += bias[ob+0]; v.y += bias[ob+1];
                v.z += bias[ob+2]; v.w += bias[ob+3];
            }
            *(float4*)(out + (size_t)pos*CZ + ob) = v;
        }
    }
}

// ---------------------------------------------------------------------------
// K3: attention, block per (i, h). One q-row per thread.
//     Chunked (16-key) online softmax; packed f32x2 dot & PV update.
// ---------------------------------------------------------------------------
__global__ __launch_bounds__(256) void k_attn(const float* __restrict__ mask)
{
    __shared__ float k_s[128][32];
    __shared__ float v_s[128][32];
    __shared__ float mb_s[256];

    int i = blockIdx.x, h = blockIdx.y;
    int t = threadIdx.x;

    mb_s[t] = 1e9f * (mask[i*NN + t] - 1.0f);

    const float scale = 0.17677669529663687f;  // 1/sqrt(32)
    float2 q2[16];
    {
        const float* qp = g_q + ((size_t)(i*NN + t))*CZ + h*DH;
        #pragma unroll
        for (int u = 0; u < 8; u++) {
            float4 v = *(const float4*)(qp + u*4);
            q2[u*2+0] = make_float2(v.x*scale, v.y*scale);
            q2[u*2+1] = make_float2(v.z*scale, v.w*scale);
        }
    }
    const float* trirow = g_tri + (size_t)h*NPOS + t*NN;   // tri[h][q=t][:]

    float m = -1e30f, l = 0.0f;
    float2 acc[16];
    #pragma unroll
    for (int d = 0; d < 16; d++) acc[d] = make_float2(0.f, 0.f);

    for (int chunk = 0; chunk < 2; chunk++) {
        int jbase = chunk * 128;
        __syncthreads();
        #pragma unroll
        for (int it = 0; it < 4; it++) {
            int row = it*32 + (t >> 3);
            int c4  = t & 7;
            size_t base = ((size_t)(i*NN + jbase + row))*CZ + h*DH + c4*4;
            ((float4*)&k_s[row][0])[c4] = *(const float4*)(g_k + base);
            ((float4*)&v_s[row][0])[c4] = *(const float4*)(g_v + base);
        }
        __syncthreads();

        for (int jj0 = 0; jj0 < 128; jj0 += 16) {
            float tr[16];
            #pragma unroll
            for (int u4 = 0; u4 < 4; u4++) {
                float4 tv = *(const float4*)(trirow + jbase + jj0 + u4*4);
                tr[u4*4+0] = tv.x; tr[u4*4+1] = tv.y;
                tr[u4*4+2] = tv.z; tr[u4*4+3] = tv.w;
            }

            float s[16];
            #pragma unroll
            for (int u = 0; u < 16; u++) {
                int jj = jj0 + u;
                const float2* k2 = (const float2*)&k_s[jj][0];
                float2 d0 = make_float2(0.f,0.f), d1 = make_float2(0.f,0.f);
                #pragma unroll
                for (int dd = 0; dd < 16; dd += 2) {
                    ffma2(d0, q2[dd+0], k2[dd+0]);
                    ffma2(d1, q2[dd+1], k2[dd+1]);
                }
                s[u] = ((d0.x+d0.y)+(d1.x+d1.y)) + mb_s[jbase+jj] + tr[u];
            }

            float cm = s[0];
            #pragma unroll
            for (int u = 1; u < 16; u++) cm = fmaxf(cm, s[u]);
            float mnew = fmaxf(m, cm);
            float f = __expf(m - mnew);

            l *= f;
            float2 f2 = pack2(f);
            #pragma unroll
            for (int d = 0; d < 16; d++) fmul2(acc[d], acc[d], f2);

            #pragma unroll
            for (int u = 0; u < 16; u++) {
                float p = __expf(s[u] - mnew);
                l += p;
                float2 p2 = pack2(p);
                const float2* v2 = (const float2*)&v_s[jj0+u][0];
                #pragma unroll
                for (int d = 0; d < 16; d++)
                    ffma2(acc[d], p2, v2[d]);
            }
            m = mnew;
        }
    }

    float inv = 1.0f / l;
    size_t base = ((size_t)(i*NN + t))*CZ + h*DH;
    const float* gp = g_g + base;
    float* op = g_o + base;
    #pragma unroll
    for (int u = 0; u < 8; u++) {
        float4 gg = *(const float4*)(gp + u*4);
        float4 o4;
        o4.x = acc[u*2+0].x*inv*gg.x;
        o4.y = acc[u*2+0].y*inv*gg.y;
        o4.z = acc[u*2+1].x*inv*gg.z;
        o4.w = acc[u*2+1].y*inv*gg.w;
        *(float4*)(op + u*4) = o4;
    }
}

// ---------------------------------------------------------------------------
extern "C" void kernel_launch(void* const* d_in, const int* in_sizes, int n_in,
                              void* d_out, int out_size)
{
    const float* x     = (const float*)d_in[0];
    const float* mask  = (const float*)d_in[1];
    const float* ln_g  = (const float*)d_in[2];
    const float* ln_b  = (const float*)d_in[3];
    const float* w_tri = (const float*)d_in[4];
    const float* wq    = (const float*)d_in[5];
    const float* wk    = (const float*)d_in[6];
    const float* wv    = (const float*)d_in[7];
    const float* wg    = (const float*)d_in[8];
    const float* bg    = (const float*)d_in[9];
    const float* wo    = (const float*)d_in[10];
    const float* bo    = (const float*)d_in[11];
    float* out = (float*)d_out;

    k_ln  <<<NPOS/8, 256>>>(x, ln_g, ln_b, w_tri);
    k_gemm<<<NPOS/128, 256>>>(0, wq, nullptr, nullptr);
    k_gemm<<<NPOS/128, 256>>>(1, wk, nullptr, nullptr);
    k_gemm<<<NPOS/128, 256>>>(2, wv, nullptr, nullptr);
    k_gemm<<<NPOS/128, 256>>>(3, wg, bg,      nullptr);
    k_attn<<<dim3(NN, H), 256>>>(mask);
    k_gemm<<<NPOS/128, 256>>>(4, wo, bo, out);
}

// round 5
// speedup vs baseline: 1.3506x; 1.3506x over previous
#include <cuda_runtime.h>
#include <stdint.h>
#include <math.h>

#define NN   256
#define CZ   128
#define H    4
#define DH   32
#define NPOS (NN*NN)

// Scratch (device globals: allocation-free rule). Device-code access only.
__device__ __align__(16) float g_xn[NPOS*CZ];
__device__ __align__(16) float g_q [NPOS*CZ];
__device__ __align__(16) float g_k [NPOS*CZ];
__device__ __align__(16) float g_v [NPOS*CZ];
__device__ __align__(16) float g_g [NPOS*CZ];
__device__ __align__(16) float g_o [NPOS*CZ];
__device__ __align__(16) float g_tri[H*NPOS];

// ---- tf32 helpers -----------------------------------------------------------
__device__ __forceinline__ uint32_t f2tf32(float f) {
    uint32_t u;
    asm("cvt.rna.tf32.f32 %0, %1;" : "=r"(u) : "f"(f));
    return u;
}
__device__ __forceinline__ void mma_tf32(float* d, const uint32_t* a, const uint32_t* b) {
    asm volatile(
        "mma.sync.aligned.m16n8k8.row.col.f32.tf32.tf32.f32 "
        "{%0,%1,%2,%3}, {%4,%5,%6,%7}, {%8,%9}, {%0,%1,%2,%3};"
        : "+f"(d[0]), "+f"(d[1]), "+f"(d[2]), "+f"(d[3])
        : "r"(a[0]), "r"(a[1]), "r"(a[2]), "r"(a[3]),
          "r"(b[0]), "r"(b[1]));
}

// ---------------------------------------------------------------------------
// K1: LayerNorm over c_z (warp per position) + fused triangle bias
// ---------------------------------------------------------------------------
__global__ __launch_bounds__(256) void k_ln(
    const float* __restrict__ x,
    const float* __restrict__ ln_g,
    const float* __restrict__ ln_b,
    const float* __restrict__ w_tri)
{
    int warp = threadIdx.x >> 5;
    int lane = threadIdx.x & 31;
    int pos  = blockIdx.x * 8 + warp;          // grid = NPOS/8

    float4 v = *(const float4*)(x + (size_t)pos*CZ + lane*4);
    float s  = v.x + v.y + v.z + v.w;
    float ss = v.x*v.x + v.y*v.y + v.z*v.z + v.w*v.w;
    #pragma unroll
    for (int off = 16; off; off >>= 1) {
        s  += __shfl_xor_sync(0xffffffffu, s,  off);
        ss += __shfl_xor_sync(0xffffffffu, ss, off);
    }
    float mu  = s * (1.0f/CZ);
    float var = ss * (1.0f/CZ) - mu*mu;
    float rs  = rsqrtf(var + 1e-5f);

    float4 gg = *(const float4*)(ln_g + lane*4);
    float4 bb = *(const float4*)(ln_b + lane*4);
    float4 y;
    y.x = (v.x - mu)*rs*gg.x + bb.x;
    y.y = (v.y - mu)*rs*gg.y + bb.y;
    y.z = (v.z - mu)*rs*gg.z + bb.z;
    y.w = (v.w - mu)*rs*gg.w + bb.w;
    *(float4*)(g_xn + (size_t)pos*CZ + lane*4) = y;

    #pragma unroll
    for (int h = 0; h < H; h++) {
        float4 w = *(const float4*)(w_tri + h*CZ + lane*4);
        float d = y.x*w.x + y.y*w.y + y.z*w.z + y.w*w.w;
        #pragma unroll
        for (int off = 16; off; off >>= 1)
            d += __shfl_xor_sync(0xffffffffu, d, off);
        if (lane == 0) g_tri[h*NPOS + pos] = d;
    }
}

// ---------------------------------------------------------------------------
// Shared tf32 tensor-core GEMM tile: y[pos][o] = act(sum_c A[pos][c]*W[o][c])
// 128x128 CTA tile, 8 warps (2x4), 64x32 per warp (4x4 m16n8k8 frags).
// act: 0 none, 1 sigmoid(y+bias), 2 y+bias
// ---------------------------------------------------------------------------
__device__ __forceinline__ void gemm_tile(
    const float* __restrict__ A,
    const float* __restrict__ W,
    float* __restrict__ out,
    const float* __restrict__ bias,
    int act, int p0)
{
    __shared__ uint32_t a_s[128][33];
    __shared__ uint32_t w_s[128][33];

    int t    = threadIdx.x;
    int warp = t >> 5;
    int lane = t & 31;
    int gq   = lane >> 2;       // 0..7
    int tq   = lane & 3;        // 0..3
    int wm   = (warp >> 2) * 64;   // 0 or 64
    int wn   = (warp & 3) * 32;    // 0,32,64,96

    float acc[4][4][4];
    #pragma unroll
    for (int mi = 0; mi < 4; mi++)
        #pragma unroll
        for (int ni = 0; ni < 4; ni++)
            #pragma unroll
            for (int r = 0; r < 4; r++) acc[mi][ni][r] = 0.0f;

    for (int c0 = 0; c0 < CZ; c0 += 32) {
        if (c0) __syncthreads();
        #pragma unroll
        for (int i = 0; i < 4; i++) {
            int idx = t + i*256;             // 0..1023
            int row = idx >> 3;              // 0..127
            int cs  = idx & 7;               // 0..7 (float4 segment)
            float4 va = *(const float4*)(A + (size_t)(p0+row)*CZ + c0 + cs*4);
            a_s[row][cs*4+0] = f2tf32(va.x);
            a_s[row][cs*4+1] = f2tf32(va.y);
            a_s[row][cs*4+2] = f2tf32(va.z);
            a_s[row][cs*4+3] = f2tf32(va.w);
            float4 vw = *(const float4*)(W + (size_t)row*CZ + c0 + cs*4);
            w_s[row][cs*4+0] = f2tf32(vw.x);
            w_s[row][cs*4+1] = f2tf32(vw.y);
            w_s[row][cs*4+2] = f2tf32(vw.z);
            w_s[row][cs*4+3] = f2tf32(vw.w);
        }
        __syncthreads();

        #pragma unroll
        for (int ks = 0; ks < 4; ks++) {
            int kb = ks * 8;
            uint32_t afr[4][4], bfr[4][2];
            #pragma unroll
            for (int mi = 0; mi < 4; mi++) {
                int r = wm + mi*16 + gq;
                afr[mi][0] = a_s[r  ][kb+tq];
                afr[mi][1] = a_s[r+8][kb+tq];
                afr[mi][2] = a_s[r  ][kb+tq+4];
                afr[mi][3] = a_s[r+8][kb+tq+4];
            }
            #pragma unroll
            for (int ni = 0; ni < 4; ni++) {
                int n = wn + ni*8 + gq;
                bfr[ni][0] = w_s[n][kb+tq];
                bfr[ni][1] = w_s[n][kb+tq+4];
            }
            #pragma unroll
            for (int mi = 0; mi < 4; mi++)
                #pragma unroll
                for (int ni = 0; ni < 4; ni++)
                    mma_tf32(acc[mi][ni], afr[mi], bfr[ni]);
        }
    }

    #pragma unroll
    for (int mi = 0; mi < 4; mi++) {
        #pragma unroll
        for (int ni = 0; ni < 4; ni++) {
            int col = wn + ni*8 + tq*2;
            float b0 = 0.f, b1 = 0.f;
            if (act) { b0 = bias[col]; b1 = bias[col+1]; }
            #pragma unroll
            for (int rr = 0; rr < 2; rr++) {
                int pos = p0 + wm + mi*16 + gq + rr*8;
                float vx = acc[mi][ni][rr*2+0];
                float vy = acc[mi][ni][rr*2+1];
                if (act == 1) {
                    vx = 1.0f/(1.0f + __expf(-(vx + b0)));
                    vy = 1.0f/(1.0f + __expf(-(vy + b1)));
                } else if (act == 2) {
                    vx += b0; vy += b1;
                }
                float2 o2 = make_float2(vx, vy);
                *(float2*)(out + (size_t)pos*CZ + col) = o2;
            }
        }
    }
}

// projections: grid (NPOS/128, 4); blockIdx.y selects q/k/v/g
__global__ __launch_bounds__(256, 2) void k_proj(
    const float* __restrict__ wq, const float* __restrict__ wk,
    const float* __restrict__ wv, const float* __restrict__ wg,
    const float* __restrict__ bg)
{
    int sel = blockIdx.y;
    const float* W = (sel==0) ? wq : (sel==1) ? wk : (sel==2) ? wv : wg;
    float* out     = (sel==0) ? g_q : (sel==1) ? g_k : (sel==2) ? g_v : g_g;
    gemm_tile(g_xn, W, out, bg, (sel==3) ? 1 : 0, blockIdx.x * 128);
}

// output projection
__global__ __launch_bounds__(256, 2) void k_outp(
    const float* __restrict__ wo, const float* __restrict__ bo,
    float* __restrict__ out)
{
    gemm_tile(g_o, wo, out, bo, 2, blockIdx.x * 128);
}

// ---------------------------------------------------------------------------
// K3: attention, block per (i, h). One q-row per thread.
//     Chunked (16-key) online softmax (round-3 verified version).
// ---------------------------------------------------------------------------
__global__ __launch_bounds__(256) void k_attn(const float* __restrict__ mask)
{
    __shared__ float k_s[128][32];
    __shared__ float v_s[128][32];
    __shared__ float mb_s[256];

    int i = blockIdx.x, h = blockIdx.y;
    int t = threadIdx.x;

    mb_s[t] = 1e9f * (mask[i*NN + t] - 1.0f);

    const float scale = 0.17677669529663687f;  // 1/sqrt(32)
    float q[DH];
    {
        const float* qp = g_q + ((size_t)(i*NN + t))*CZ + h*DH;
        #pragma unroll
        for (int u = 0; u < 8; u++) {
            float4 v = *(const float4*)(qp + u*4);
            q[u*4+0] = v.x*scale; q[u*4+1] = v.y*scale;
            q[u*4+2] = v.z*scale; q[u*4+3] = v.w*scale;
        }
    }
    const float* trirow = g_tri + (size_t)h*NPOS + t*NN;

    float m = -1e30f, l = 0.0f;
    float acc[DH];
    #pragma unroll
    for (int d = 0; d < DH; d++) acc[d] = 0.0f;

    for (int chunk = 0; chunk < 2; chunk++) {
        int jbase = chunk * 128;
        __syncthreads();
        #pragma unroll
        for (int it = 0; it < 4; it++) {
            int row = it*32 + (t >> 3);
            int c4  = t & 7;
            size_t base = ((size_t)(i*NN + jbase + row))*CZ + h*DH + c4*4;
            ((float4*)&k_s[row][0])[c4] = *(const float4*)(g_k + base);
            ((float4*)&v_s[row][0])[c4] = *(const float4*)(g_v + base);
        }
        __syncthreads();

        for (int jj0 = 0; jj0 < 128; jj0 += 16) {
            float tr[16];
            #pragma unroll
            for (int u4 = 0; u4 < 4; u4++) {
                float4 tv = *(const float4*)(trirow + jbase + jj0 + u4*4);
                tr[u4*4+0] = tv.x; tr[u4*4+1] = tv.y;
                tr[u4*4+2] = tv.z; tr[u4*4+3] = tv.w;
            }

            float s[16];
            #pragma unroll
            for (int u = 0; u < 16; u++) {
                int jj = jj0 + u;
                float s0 = 0.f, s1 = 0.f, s2 = 0.f, s3 = 0.f;
                #pragma unroll
                for (int d = 0; d < DH; d += 4) {
                    s0 += q[d+0]*k_s[jj][d+0];
                    s1 += q[d+1]*k_s[jj][d+1];
                    s2 += q[d+2]*k_s[jj][d+2];
                    s3 += q[d+3]*k_s[jj][d+3];
                }
                s[u] = ((s0+s1)+(s2+s3)) + mb_s[jbase+jj] + tr[u];
            }

            float cm = s[0];
            #pragma unroll
            for (int u = 1; u < 16; u++) cm = fmaxf(cm, s[u]);
            float mnew = fmaxf(m, cm);
            float f = __expf(m - mnew);

            l *= f;
            #pragma unroll
            for (int d = 0; d < DH; d++) acc[d] *= f;

            #pragma unroll
            for (int u = 0; u < 16; u++) {
                float p = __expf(s[u] - mnew);
                l += p;
                int jj = jj0 + u;
                #pragma unroll
                for (int d = 0; d < DH; d += 4) {
                    float4 vv = *(const float4*)&v_s[jj][d];
                    acc[d+0] += p*vv.x; acc[d+1] += p*vv.y;
                    acc[d+2] += p*vv.z; acc[d+3] += p*vv.w;
                }
            }
            m = mnew;
        }
    }

    float inv = 1.0f / l;
    size_t base = ((size_t)(i*NN + t))*CZ + h*DH;
    const float* gp = g_g + base;
    float* op = g_o + base;
    #pragma unroll
    for (int u = 0; u < 8; u++) {
        float4 gg = *(const float4*)(gp + u*4);
        float4 o4;
        o4.x = acc[u*4+0]*inv*gg.x;
        o4.y = acc[u*4+1]*inv*gg.y;
        o4.z = acc[u*4+2]*inv*gg.z;
        o4.w = acc[u*4+3]*inv*gg.w;
        *(float4*)(op + u*4) = o4;
    }
}

// ---------------------------------------------------------------------------
extern "C" void kernel_launch(void* const* d_in, const int* in_sizes, int n_in,
                              void* d_out, int out_size)
{
    const float* x     = (const float*)d_in[0];
    const float* mask  = (const float*)d_in[1];
    const float* ln_g  = (const float*)d_in[2];
    const float* ln_b  = (const float*)d_in[3];
    const float* w_tri = (const float*)d_in[4];
    const float* wq    = (const float*)d_in[5];
    const float* wk    = (const float*)d_in[6];
    const float* wv    = (const float*)d_in[7];
    const float* wg    = (const float*)d_in[8];
    const float* bg    = (const float*)d_in[9];
    const float* wo    = (const float*)d_in[10];
    const float* bo    = (const float*)d_in[11];
    float* out = (float*)d_out;

    k_ln  <<<NPOS/8, 256>>>(x, ln_g, ln_b, w_tri);
    k_proj<<<dim3(NPOS/128, 4), 256>>>(wq, wk, wv, wg, bg);
    k_attn<<<dim3(NN, H), 256>>>(mask);
    k_outp<<<NPOS/128, 256>>>(wo, bo, out);
}

// round 6
// speedup vs baseline: 2.5699x; 1.9028x over previous
#include <cuda_runtime.h>
#include <stdint.h>
#include <math.h>

#define NN   256
#define CZ   128
#define H    4
#define DH   32
#define NPOS (NN*NN)

// Scratch (device globals: allocation-free rule). Device-code access only.
__device__ __align__(16) float g_xn[NPOS*CZ];
__device__ __align__(16) float g_q [NPOS*CZ];
__device__ __align__(16) float g_k [NPOS*CZ];
__device__ __align__(16) float g_v [NPOS*CZ];
__device__ __align__(16) float g_g [NPOS*CZ];
__device__ __align__(16) float g_o [NPOS*CZ];
__device__ __align__(16) float g_tri[H*NPOS];

// ---- tf32 helpers -----------------------------------------------------------
__device__ __forceinline__ uint32_t f2tf32(float f) {
    uint32_t u;
    asm("cvt.rna.tf32.f32 %0, %1;" : "=r"(u) : "f"(f));
    return u;
}
__device__ __forceinline__ void mma_tf32(float* d, const uint32_t* a, const uint32_t* b) {
    asm volatile(
        "mma.sync.aligned.m16n8k8.row.col.f32.tf32.tf32.f32 "
        "{%0,%1,%2,%3}, {%4,%5,%6,%7}, {%8,%9}, {%0,%1,%2,%3};"
        : "+f"(d[0]), "+f"(d[1]), "+f"(d[2]), "+f"(d[3])
        : "r"(a[0]), "r"(a[1]), "r"(a[2]), "r"(a[3]),
          "r"(b[0]), "r"(b[1]));
}

// ---------------------------------------------------------------------------
// K1: LayerNorm over c_z (warp per position) + fused triangle bias
// ---------------------------------------------------------------------------
__global__ __launch_bounds__(256) void k_ln(
    const float* __restrict__ x,
    const float* __restrict__ ln_g,
    const float* __restrict__ ln_b,
    const float* __restrict__ w_tri)
{
    int warp = threadIdx.x >> 5;
    int lane = threadIdx.x & 31;
    int pos  = blockIdx.x * 8 + warp;          // grid = NPOS/8

    float4 v = *(const float4*)(x + (size_t)pos*CZ + lane*4);
    float s  = v.x + v.y + v.z + v.w;
    float ss = v.x*v.x + v.y*v.y + v.z*v.z + v.w*v.w;
    #pragma unroll
    for (int off = 16; off; off >>= 1) {
        s  += __shfl_xor_sync(0xffffffffu, s,  off);
        ss += __shfl_xor_sync(0xffffffffu, ss, off);
    }
    float mu  = s * (1.0f/CZ);
    float var = ss * (1.0f/CZ) - mu*mu;
    float rs  = rsqrtf(var + 1e-5f);

    float4 gg = *(const float4*)(ln_g + lane*4);
    float4 bb = *(const float4*)(ln_b + lane*4);
    float4 y;
    y.x = (v.x - mu)*rs*gg.x + bb.x;
    y.y = (v.y - mu)*rs*gg.y + bb.y;
    y.z = (v.z - mu)*rs*gg.z + bb.z;
    y.w = (v.w - mu)*rs*gg.w + bb.w;
    *(float4*)(g_xn + (size_t)pos*CZ + lane*4) = y;

    #pragma unroll
    for (int h = 0; h < H; h++) {
        float4 w = *(const float4*)(w_tri + h*CZ + lane*4);
        float d = y.x*w.x + y.y*w.y + y.z*w.z + y.w*w.w;
        #pragma unroll
        for (int off = 16; off; off >>= 1)
            d += __shfl_xor_sync(0xffffffffu, d, off);
        if (lane == 0) g_tri[h*NPOS + pos] = d;
    }
}

// ---------------------------------------------------------------------------
// Shared tf32 tensor-core GEMM tile: y[pos][o] = act(sum_c A[pos][c]*W[o][c])
// 128x128 CTA tile, 8 warps (2x4), 64x32 per warp (4x4 m16n8k8 frags).
// smem stride 36 (== 4 mod 32): frag-load bank = 4*gq + tq -> conflict-free.
// act: 0 none, 1 sigmoid(y+bias), 2 y+bias
// ---------------------------------------------------------------------------
__device__ __forceinline__ void gemm_tile(
    const float* __restrict__ A,
    const float* __restrict__ W,
    float* __restrict__ out,
    const float* __restrict__ bias,
    int act, int p0)
{
    __shared__ uint32_t a_s[128*36];
    __shared__ uint32_t w_s[128*36];

    int t    = threadIdx.x;
    int warp = t >> 5;
    int lane = t & 31;
    int gq   = lane >> 2;       // 0..7
    int tq   = lane & 3;        // 0..3
    int wm   = (warp >> 2) * 64;   // 0 or 64
    int wn   = (warp & 3) * 32;    // 0,32,64,96

    float acc[4][4][4];
    #pragma unroll
    for (int mi = 0; mi < 4; mi++)
        #pragma unroll
        for (int ni = 0; ni < 4; ni++)
            #pragma unroll
            for (int r = 0; r < 4; r++) acc[mi][ni][r] = 0.0f;

    for (int c0 = 0; c0 < CZ; c0 += 32) {
        if (c0) __syncthreads();
        #pragma unroll
        for (int i = 0; i < 4; i++) {
            int idx = t + i*256;             // 0..1023
            int row = idx >> 3;              // 0..127
            int cs  = idx & 7;               // float4 segment
            float4 va = *(const float4*)(A + (size_t)(p0+row)*CZ + c0 + cs*4);
            uint4 ua;
            ua.x = f2tf32(va.x); ua.y = f2tf32(va.y);
            ua.z = f2tf32(va.z); ua.w = f2tf32(va.w);
            *(uint4*)&a_s[row*36 + cs*4] = ua;
            float4 vw = *(const float4*)(W + (size_t)row*CZ + c0 + cs*4);
            uint4 uw;
            uw.x = f2tf32(vw.x); uw.y = f2tf32(vw.y);
            uw.z = f2tf32(vw.z); uw.w = f2tf32(vw.w);
            *(uint4*)&w_s[row*36 + cs*4] = uw;
        }
        __syncthreads();

        #pragma unroll
        for (int ks = 0; ks < 4; ks++) {
            int kb = ks * 8;
            uint32_t afr[4][4], bfr[4][2];
            #pragma unroll
            for (int mi = 0; mi < 4; mi++) {
                int r = wm + mi*16 + gq;
                afr[mi][0] = a_s[r*36     + kb+tq];
                afr[mi][1] = a_s[(r+8)*36 + kb+tq];
                afr[mi][2] = a_s[r*36     + kb+tq+4];
                afr[mi][3] = a_s[(r+8)*36 + kb+tq+4];
            }
            #pragma unroll
            for (int ni = 0; ni < 4; ni++) {
                int n = wn + ni*8 + gq;
                bfr[ni][0] = w_s[n*36 + kb+tq];
                bfr[ni][1] = w_s[n*36 + kb+tq+4];
            }
            #pragma unroll
            for (int mi = 0; mi < 4; mi++)
                #pragma unroll
                for (int ni = 0; ni < 4; ni++)
                    mma_tf32(acc[mi][ni], afr[mi], bfr[ni]);
        }
    }

    #pragma unroll
    for (int mi = 0; mi < 4; mi++) {
        #pragma unroll
        for (int ni = 0; ni < 4; ni++) {
            int col = wn + ni*8 + tq*2;
            float b0 = 0.f, b1 = 0.f;
            if (act) { b0 = bias[col]; b1 = bias[col+1]; }
            #pragma unroll
            for (int rr = 0; rr < 2; rr++) {
                int pos = p0 + wm + mi*16 + gq + rr*8;
                float vx = acc[mi][ni][rr*2+0];
                float vy = acc[mi][ni][rr*2+1];
                if (act == 1) {
                    vx = 1.0f/(1.0f + __expf(-(vx + b0)));
                    vy = 1.0f/(1.0f + __expf(-(vy + b1)));
                } else if (act == 2) {
                    vx += b0; vy += b1;
                }
                *(float2*)(out + (size_t)pos*CZ + col) = make_float2(vx, vy);
            }
        }
    }
}

__global__ __launch_bounds__(256, 2) void k_proj(
    const float* __restrict__ wq, const float* __restrict__ wk,
    const float* __restrict__ wv, const float* __restrict__ wg,
    const float* __restrict__ bg)
{
    int sel = blockIdx.y;
    const float* W = (sel==0) ? wq : (sel==1) ? wk : (sel==2) ? wv : wg;
    float* out     = (sel==0) ? g_q : (sel==1) ? g_k : (sel==2) ? g_v : g_g;
    gemm_tile(g_xn, W, out, bg, (sel==3) ? 1 : 0, blockIdx.x * 128);
}

__global__ __launch_bounds__(256, 2) void k_outp(
    const float* __restrict__ wo, const float* __restrict__ bo,
    float* __restrict__ out)
{
    gemm_tile(g_o, wo, out, bo, 2, blockIdx.x * 128);
}

// ---------------------------------------------------------------------------
// K3: tensor-core attention. Block per (i,h), 8 warps x 32 q-rows.
// Flash-style over 4 j-blocks of 64: S = Q·K^T (tf32 mma) + biases,
// online softmax on acc fragments, P re-shuffled into A-frag layout, PV mma.
// ---------------------------------------------------------------------------
__global__ __launch_bounds__(256) void k_attn(const float* __restrict__ mask)
{
    __shared__ uint32_t sbuf[256*36];   // Q stage, then K[64][36] | V[64][36]
    __shared__ float mb_s[256];

    int i = blockIdx.x, h = blockIdx.y;
    int t = threadIdx.x;
    int warp = t >> 5, lane = t & 31;
    int gq = lane >> 2, tq = lane & 3;
    int wrow = warp * 32;

    mb_s[t] = 1e9f * (mask[i*NN + t] - 1.0f);

    const float scale = 0.17677669529663687f;  // 1/sqrt(32)
    // stage Q (scaled, tf32)
    #pragma unroll
    for (int it = 0; it < 8; it++) {
        int idx = t + it*256;               // 0..2047
        int row = idx >> 3, c4 = idx & 7;
        float4 v = *(const float4*)(g_q + ((size_t)(i*NN+row))*CZ + h*DH + c4*4);
        uint4 u;
        u.x = f2tf32(v.x*scale); u.y = f2tf32(v.y*scale);
        u.z = f2tf32(v.z*scale); u.w = f2tf32(v.w*scale);
        *(uint4*)&sbuf[row*36 + c4*4] = u;
    }
    __syncthreads();

    // Q fragments (persist in registers)
    uint32_t qf[2][4][4];
    #pragma unroll
    for (int mi = 0; mi < 2; mi++)
        #pragma unroll
        for (int ks = 0; ks < 4; ks++) {
            int r0 = wrow + mi*16 + gq;
            qf[mi][ks][0] = sbuf[r0*36     + ks*8 + tq];
            qf[mi][ks][1] = sbuf[(r0+8)*36 + ks*8 + tq];
            qf[mi][ks][2] = sbuf[r0*36     + ks*8 + tq + 4];
            qf[mi][ks][3] = sbuf[(r0+8)*36 + ks*8 + tq + 4];
        }
    __syncthreads();

    uint32_t* k_s = sbuf;
    uint32_t* v_s = sbuf + 64*36;

    float mrun[2][2], lrun[2][2];
    float oacc[2][4][4];
    #pragma unroll
    for (int mi = 0; mi < 2; mi++) {
        mrun[mi][0] = mrun[mi][1] = -1e30f;
        lrun[mi][0] = lrun[mi][1] = 0.0f;
        #pragma unroll
        for (int nd = 0; nd < 4; nd++)
            #pragma unroll
            for (int r = 0; r < 4; r++) oacc[mi][nd][r] = 0.0f;
    }

    const float* trib = g_tri + (size_t)h*NPOS;

    for (int jb = 0; jb < 4; jb++) {
        int j0 = jb * 64;
        if (jb) __syncthreads();
        // stage K,V (tf32)
        #pragma unroll
        for (int it = 0; it < 2; it++) {
            int idx = t + it*256;           // 0..511
            int row = idx >> 3, c4 = idx & 7;
            size_t gb = ((size_t)(i*NN + j0 + row))*CZ + h*DH + c4*4;
            float4 kv = *(const float4*)(g_k + gb);
            float4 vv = *(const float4*)(g_v + gb);
            uint4 uk, uv;
            uk.x = f2tf32(kv.x); uk.y = f2tf32(kv.y);
            uk.z = f2tf32(kv.z); uk.w = f2tf32(kv.w);
            uv.x = f2tf32(vv.x); uv.y = f2tf32(vv.y);
            uv.z = f2tf32(vv.z); uv.w = f2tf32(vv.w);
            *(uint4*)&k_s[row*36 + c4*4] = uk;
            *(uint4*)&v_s[row*36 + c4*4] = uv;
        }
        __syncthreads();

        // S = Q K^T
        float sacc[2][8][4];
        #pragma unroll
        for (int mi = 0; mi < 2; mi++)
            #pragma unroll
            for (int ni = 0; ni < 8; ni++)
                #pragma unroll
                for (int r = 0; r < 4; r++) sacc[mi][ni][r] = 0.0f;

        #pragma unroll
        for (int ks = 0; ks < 4; ks++) {
            uint32_t bf[8][2];
            #pragma unroll
            for (int ni = 0; ni < 8; ni++) {
                int base = (ni*8 + gq)*36 + ks*8 + tq;
                bf[ni][0] = k_s[base];
                bf[ni][1] = k_s[base + 4];
            }
            #pragma unroll
            for (int mi = 0; mi < 2; mi++)
                #pragma unroll
                for (int ni = 0; ni < 8; ni++)
                    mma_tf32(sacc[mi][ni], qf[mi][ks], bf[ni]);
        }

        // + mask bias + triangle bias
        #pragma unroll
        for (int mi = 0; mi < 2; mi++) {
            int r0 = wrow + mi*16 + gq;
            #pragma unroll
            for (int ni = 0; ni < 8; ni++) {
                int j = j0 + ni*8 + tq*2;
                float2 t0 = *(const float2*)(trib + (size_t)r0*NN + j);
                float2 t1 = *(const float2*)(trib + (size_t)(r0+8)*NN + j);
                float mb0 = mb_s[j], mb1 = mb_s[j+1];
                sacc[mi][ni][0] += t0.x + mb0;
                sacc[mi][ni][1] += t0.y + mb1;
                sacc[mi][ni][2] += t1.x + mb0;
                sacc[mi][ni][3] += t1.y + mb1;
            }
        }

        // online softmax (rows gq / gq+8 per m-tile; quad = same gq, tq 0..3)
        #pragma unroll
        for (int mi = 0; mi < 2; mi++) {
            float mx0 = -1e30f, mx1 = -1e30f;
            #pragma unroll
            for (int ni = 0; ni < 8; ni++) {
                mx0 = fmaxf(mx0, fmaxf(sacc[mi][ni][0], sacc[mi][ni][1]));
                mx1 = fmaxf(mx1, fmaxf(sacc[mi][ni][2], sacc[mi][ni][3]));
            }
            mx0 = fmaxf(mx0, __shfl_xor_sync(0xffffffffu, mx0, 1));
            mx0 = fmaxf(mx0, __shfl_xor_sync(0xffffffffu, mx0, 2));
            mx1 = fmaxf(mx1, __shfl_xor_sync(0xffffffffu, mx1, 1));
            mx1 = fmaxf(mx1, __shfl_xor_sync(0xffffffffu, mx1, 2));
            float mn0 = fmaxf(mrun[mi][0], mx0);
            float mn1 = fmaxf(mrun[mi][1], mx1);
            float f0 = __expf(mrun[mi][0] - mn0);
            float f1 = __expf(mrun[mi][1] - mn1);
            mrun[mi][0] = mn0; mrun[mi][1] = mn1;
            float la0 = lrun[mi][0]*f0, la1 = lrun[mi][1]*f1;
            #pragma unroll
            for (int nd = 0; nd < 4; nd++) {
                oacc[mi][nd][0] *= f0; oacc[mi][nd][1] *= f0;
                oacc[mi][nd][2] *= f1; oacc[mi][nd][3] *= f1;
            }
            #pragma unroll
            for (int ni = 0; ni < 8; ni++) {
                float p0 = __expf(sacc[mi][ni][0] - mn0);
                float p1 = __expf(sacc[mi][ni][1] - mn0);
                float p2 = __expf(sacc[mi][ni][2] - mn1);
                float p3 = __expf(sacc[mi][ni][3] - mn1);
                uint32_t u0 = f2tf32(p0), u1 = f2tf32(p1);
                uint32_t u2 = f2tf32(p2), u3 = f2tf32(p3);
                sacc[mi][ni][0] = __uint_as_float(u0);
                sacc[mi][ni][1] = __uint_as_float(u1);
                sacc[mi][ni][2] = __uint_as_float(u2);
                sacc[mi][ni][3] = __uint_as_float(u3);
                la0 += __uint_as_float(u0) + __uint_as_float(u1);
                la1 += __uint_as_float(u2) + __uint_as_float(u3);
            }
            lrun[mi][0] = la0; lrun[mi][1] = la1;
        }

        // O += P V (P acc layout -> A-frag layout via quad shuffles)
        int srcA = (lane & ~3) | (tq >> 1);
        bool odd = (tq & 1);
        #pragma unroll
        for (int ks2 = 0; ks2 < 8; ks2++) {
            uint32_t bf[4][2];
            #pragma unroll
            for (int nd = 0; nd < 4; nd++) {
                bf[nd][0] = v_s[(ks2*8 + tq)*36     + nd*8 + gq];
                bf[nd][1] = v_s[(ks2*8 + tq + 4)*36 + nd*8 + gq];
            }
            #pragma unroll
            for (int mi = 0; mi < 2; mi++) {
                float c0 = sacc[mi][ks2][0], c1 = sacc[mi][ks2][1];
                float c2 = sacc[mi][ks2][2], c3 = sacc[mi][ks2][3];
                float l0a = __shfl_sync(0xffffffffu, c0, srcA);
                float h0a = __shfl_sync(0xffffffffu, c1, srcA);
                float l1a = __shfl_sync(0xffffffffu, c2, srcA);
                float h1a = __shfl_sync(0xffffffffu, c3, srcA);
                float l0b = __shfl_sync(0xffffffffu, c0, srcA+2);
                float h0b = __shfl_sync(0xffffffffu, c1, srcA+2);
                float l1b = __shfl_sync(0xffffffffu, c2, srcA+2);
                float h1b = __shfl_sync(0xffffffffu, c3, srcA+2);
                uint32_t af[4];
                af[0] = __float_as_uint(odd ? h0a : l0a);
                af[1] = __float_as_uint(odd ? h1a : l1a);
                af[2] = __float_as_uint(odd ? h0b : l0b);
                af[3] = __float_as_uint(odd ? h1b : l1b);
                #pragma unroll
                for (int nd = 0; nd < 4; nd++)
                    mma_tf32(oacc[mi][nd], af, bf[nd]);
            }
        }
    }

    // epilogue: normalize, gate, store
    #pragma unroll
    for (int mi = 0; mi < 2; mi++) {
        float l0 = lrun[mi][0];
        l0 += __shfl_xor_sync(0xffffffffu, l0, 1);
        l0 += __shfl_xor_sync(0xffffffffu, l0, 2);
        float l1 = lrun[mi][1];
        l1 += __shfl_xor_sync(0xffffffffu, l1, 1);
        l1 += __shfl_xor_sync(0xffffffffu, l1, 2);
        float inv0 = 1.0f / l0, inv1 = 1.0f / l1;
        int r0 = wrow + mi*16 + gq;
        #pragma unroll
        for (int nd = 0; nd < 4; nd++) {
            int d = h*DH + nd*8 + tq*2;
            size_t b0 = ((size_t)(i*NN + r0))*CZ + d;
            size_t b1 = ((size_t)(i*NN + r0 + 8))*CZ + d;
            float2 gg0 = *(const float2*)(g_g + b0);
            float2 gg1 = *(const float2*)(g_g + b1);
            *(float2*)(g_o + b0) =
                make_float2(oacc[mi][nd][0]*inv0*gg0.x, oacc[mi][nd][1]*inv0*gg0.y);
            *(float2*)(g_o + b1) =
                make_float2(oacc[mi][nd][2]*inv1*gg1.x, oacc[mi][nd][3]*inv1*gg1.y);
        }
    }
}

// ---------------------------------------------------------------------------
extern "C" void kernel_launch(void* const* d_in, const int* in_sizes, int n_in,
                              void* d_out, int out_size)
{
    const float* x     = (const float*)d_in[0];
    const float* mask  = (const float*)d_in[1];
    const float* ln_g  = (const float*)d_in[2];
    const float* ln_b  = (const float*)d_in[3];
    const float* w_tri = (const float*)d_in[4];
    const float* wq    = (const float*)d_in[5];
    const float* wk    = (const float*)d_in[6];
    const float* wv    = (const float*)d_in[7];
    const float* wg    = (const float*)d_in[8];
    const float* bg    = (const float*)d_in[9];
    const float* wo    = (const float*)d_in[10];
    const float* bo    = (const float*)d_in[11];
    float* out = (float*)d_out;

    k_ln  <<<NPOS/8, 256>>>(x, ln_g, ln_b, w_tri);
    k_proj<<<dim3(NPOS/128, 4), 256>>>(wq, wk, wv, wg, bg);
    k_attn<<<dim3(NN, H), 256>>>(mask);
    k_outp<<<NPOS/128, 256>>>(wo, bo, out);
}

// round 7
// speedup vs baseline: 2.7208x; 1.0587x over previous
#include <cuda_runtime.h>
#include <stdint.h>
#include <math.h>

#define NN   256
#define CZ   128
#define H    4
#define DH   32
#define NPOS (NN*NN)

// Scratch (device globals; device-code access only).
// tf32-bit buffers are uint32_t; fp32 buffers are float.
__device__ __align__(16) uint32_t g_xn[NPOS*CZ];
__device__ __align__(16) uint32_t g_q [NPOS*CZ];
__device__ __align__(16) uint32_t g_k [NPOS*CZ];
__device__ __align__(16) uint32_t g_v [NPOS*CZ];
__device__ __align__(16) float    g_g [NPOS*CZ];
__device__ __align__(16) uint32_t g_o [NPOS*CZ];
__device__ __align__(16) float    g_tri[H*NPOS];
__device__ __align__(16) uint32_t g_wt[5*CZ*CZ];   // wq*scale, wk, wv, wg, wo (tf32)

// ---- helpers ---------------------------------------------------------------
__device__ __forceinline__ uint32_t f2tf32(float f) {
    uint32_t u;
    asm("cvt.rna.tf32.f32 %0, %1;" : "=r"(u) : "f"(f));
    return u;
}
__device__ __forceinline__ void mma_tf32(float* d, const uint32_t* a, const uint32_t* b) {
    asm volatile(
        "mma.sync.aligned.m16n8k8.row.col.f32.tf32.tf32.f32 "
        "{%0,%1,%2,%3}, {%4,%5,%6,%7}, {%8,%9}, {%0,%1,%2,%3};"
        : "+f"(d[0]), "+f"(d[1]), "+f"(d[2]), "+f"(d[3])
        : "r"(a[0]), "r"(a[1]), "r"(a[2]), "r"(a[3]),
          "r"(b[0]), "r"(b[1]));
}
__device__ __forceinline__ void cp16(uint32_t* smem_dst, const uint32_t* gsrc) {
    uint32_t sa = (uint32_t)__cvta_generic_to_shared(smem_dst);
    asm volatile("cp.async.ca.shared.global [%0], [%1], 16;"
                 :: "r"(sa), "l"(gsrc) : "memory");
}
#define CP_COMMIT() asm volatile("cp.async.commit_group;" ::: "memory")
#define CP_WAIT0()  asm volatile("cp.async.wait_group 0;" ::: "memory")

// ---------------------------------------------------------------------------
// K0: weight prep — convert 5 weight matrices to tf32 (wq folded with scale)
// ---------------------------------------------------------------------------
__global__ __launch_bounds__(256) void k_prep(
    const float* __restrict__ wq, const float* __restrict__ wk,
    const float* __restrict__ wv, const float* __restrict__ wg,
    const float* __restrict__ wo)
{
    int sel = blockIdx.y;
    int idx = blockIdx.x * 256 + threadIdx.x;        // 0..16383
    const float* src = (sel==0) ? wq : (sel==1) ? wk : (sel==2) ? wv
                     : (sel==3) ? wg : wo;
    float v = src[idx];
    if (sel == 0) v *= 0.17677669529663687f;          // 1/sqrt(DH)
    g_wt[sel*CZ*CZ + idx] = f2tf32(v);
}

// ---------------------------------------------------------------------------
// K1: LayerNorm over c_z (warp per position) + fused triangle bias.
//     Writes xn as tf32 bits (only GEMMs consume it).
// ---------------------------------------------------------------------------
__global__ __launch_bounds__(256) void k_ln(
    const float* __restrict__ x,
    const float* __restrict__ ln_g,
    const float* __restrict__ ln_b,
    const float* __restrict__ w_tri)
{
    int warp = threadIdx.x >> 5;
    int lane = threadIdx.x & 31;
    int pos  = blockIdx.x * 8 + warp;

    float4 v = *(const float4*)(x + (size_t)pos*CZ + lane*4);
    float s  = v.x + v.y + v.z + v.w;
    float ss = v.x*v.x + v.y*v.y + v.z*v.z + v.w*v.w;
    #pragma unroll
    for (int off = 16; off; off >>= 1) {
        s  += __shfl_xor_sync(0xffffffffu, s,  off);
        ss += __shfl_xor_sync(0xffffffffu, ss, off);
    }
    float mu  = s * (1.0f/CZ);
    float var = ss * (1.0f/CZ) - mu*mu;
    float rs  = rsqrtf(var + 1e-5f);

    float4 gg = *(const float4*)(ln_g + lane*4);
    float4 bb = *(const float4*)(ln_b + lane*4);
    float4 y;
    y.x = (v.x - mu)*rs*gg.x + bb.x;
    y.y = (v.y - mu)*rs*gg.y + bb.y;
    y.z = (v.z - mu)*rs*gg.z + bb.z;
    y.w = (v.w - mu)*rs*gg.w + bb.w;
    uint4 u;
    u.x = f2tf32(y.x); u.y = f2tf32(y.y);
    u.z = f2tf32(y.z); u.w = f2tf32(y.w);
    *(uint4*)(g_xn + (size_t)pos*CZ + lane*4) = u;

    #pragma unroll
    for (int h = 0; h < H; h++) {
        float4 w = *(const float4*)(w_tri + h*CZ + lane*4);
        float d = y.x*w.x + y.y*w.y + y.z*w.z + y.w*w.w;
        #pragma unroll
        for (int off = 16; off; off >>= 1)
            d += __shfl_xor_sync(0xffffffffu, d, off);
        if (lane == 0) g_tri[h*NPOS + pos] = d;
    }
}

// ---------------------------------------------------------------------------
// tf32 tensor-core GEMM: 128x128 CTA tile, 8 warps (2x4), 64x32 per warp.
// Inputs already tf32. cp.async double-buffered K-chunks (32), 1 sync/chunk.
// smem stride 36 -> conflict-free fragment loads.
// act: 0 -> store tf32 bits; 1 -> sigmoid(y+bias) fp32; 2 -> y+bias fp32
// ---------------------------------------------------------------------------
#define GSTG (128*36)

__device__ __forceinline__ void gemm_stage(
    const uint32_t* __restrict__ A, const uint32_t* __restrict__ W,
    uint32_t* as, uint32_t* ws, int p0, int c0, int t)
{
    #pragma unroll
    for (int i = 0; i < 4; i++) {
        int idx = t + i*256;             // 0..1023
        int row = idx >> 3;              // 0..127
        int cs  = idx & 7;
        cp16(as + row*36 + cs*4, A + (size_t)(p0+row)*CZ + c0 + cs*4);
        cp16(ws + row*36 + cs*4, W + (size_t)row*CZ + c0 + cs*4);
    }
}

__device__ __forceinline__ void gemm_tile(
    const uint32_t* __restrict__ A,
    const uint32_t* __restrict__ W,
    float* __restrict__ outf,
    uint32_t* __restrict__ outt,
    const float* __restrict__ bias,
    int act, int p0)
{
    extern __shared__ uint32_t dyn[];    // [2][GSTG] A | [2][GSTG] W = 73728 B
    int t    = threadIdx.x;
    int warp = t >> 5;
    int lane = t & 31;
    int gq   = lane >> 2;
    int tq   = lane & 3;
    int wm   = (warp >> 2) * 64;
    int wn   = (warp & 3) * 32;

    float acc[4][4][4];
    #pragma unroll
    for (int mi = 0; mi < 4; mi++)
        #pragma unroll
        for (int ni = 0; ni < 4; ni++)
            #pragma unroll
            for (int r = 0; r < 4; r++) acc[mi][ni][r] = 0.0f;

    gemm_stage(A, W, dyn, dyn + 2*GSTG, p0, 0, t);
    CP_COMMIT();
    CP_WAIT0();
    __syncthreads();

    for (int c = 0; c < 4; c++) {
        if (c < 3) {
            int nb = (c+1) & 1;
            gemm_stage(A, W, dyn + nb*GSTG, dyn + 2*GSTG + nb*GSTG,
                       p0, (c+1)*32, t);
            CP_COMMIT();
        }
        const uint32_t* as = dyn + (c&1)*GSTG;
        const uint32_t* ws = dyn + 2*GSTG + (c&1)*GSTG;

        #pragma unroll
        for (int ks = 0; ks < 4; ks++) {
            int kb = ks * 8;
            uint32_t afr[4][4], bfr[4][2];
            #pragma unroll
            for (int mi = 0; mi < 4; mi++) {
                int r = wm + mi*16 + gq;
                afr[mi][0] = as[r*36     + kb+tq];
                afr[mi][1] = as[(r+8)*36 + kb+tq];
                afr[mi][2] = as[r*36     + kb+tq+4];
                afr[mi][3] = as[(r+8)*36 + kb+tq+4];
            }
            #pragma unroll
            for (int ni = 0; ni < 4; ni++) {
                int n = wn + ni*8 + gq;
                bfr[ni][0] = ws[n*36 + kb+tq];
                bfr[ni][1] = ws[n*36 + kb+tq+4];
            }
            #pragma unroll
            for (int mi = 0; mi < 4; mi++)
                #pragma unroll
                for (int ni = 0; ni < 4; ni++)
                    mma_tf32(acc[mi][ni], afr[mi], bfr[ni]);
        }
        if (c < 3) {
            CP_WAIT0();
            __syncthreads();
        }
    }

    #pragma unroll
    for (int mi = 0; mi < 4; mi++) {
        #pragma unroll
        for (int ni = 0; ni < 4; ni++) {
            int col = wn + ni*8 + tq*2;
            float b0 = 0.f, b1 = 0.f;
            if (act) { b0 = bias[col]; b1 = bias[col+1]; }
            #pragma unroll
            for (int rr = 0; rr < 2; rr++) {
                int pos = p0 + wm + mi*16 + gq + rr*8;
                float vx = acc[mi][ni][rr*2+0];
                float vy = acc[mi][ni][rr*2+1];
                if (act == 0) {
                    *(uint2*)(outt + (size_t)pos*CZ + col) =
                        make_uint2(f2tf32(vx), f2tf32(vy));
                } else if (act == 1) {
                    vx = 1.0f/(1.0f + __expf(-(vx + b0)));
                    vy = 1.0f/(1.0f + __expf(-(vy + b1)));
                    *(float2*)(outf + (size_t)pos*CZ + col) = make_float2(vx, vy);
                } else {
                    *(float2*)(outf + (size_t)pos*CZ + col) =
                        make_float2(vx + b0, vy + b1);
                }
            }
        }
    }
}

__global__ __launch_bounds__(256, 2) void k_proj(const float* __restrict__ bg)
{
    int sel = blockIdx.y;
    const uint32_t* W = g_wt + (size_t)sel*CZ*CZ;
    uint32_t* outt = (sel==0) ? g_q : (sel==1) ? g_k : (sel==2) ? g_v : nullptr;
    gemm_tile(g_xn, W, g_g, outt, bg, (sel==3) ? 1 : 0, blockIdx.x * 128);
}

__global__ __launch_bounds__(256, 2) void k_outp(
    const float* __restrict__ bo, float* __restrict__ out)
{
    gemm_tile(g_o, g_wt + (size_t)4*CZ*CZ, out, nullptr, bo, 2, blockIdx.x * 128);
}

// ---------------------------------------------------------------------------
// K3: tensor-core attention. Block per (i,h), 8 warps x 32 q-rows.
// Q/K/V already tf32 (scale folded into wq). cp.async double-buffered K/V.
// ---------------------------------------------------------------------------
#define KVSTG (64*36)

__global__ __launch_bounds__(256) void k_attn(const float* __restrict__ mask)
{
    __shared__ uint32_t sbuf[256*36];   // Q stage; then K[2][KVSTG] | V[2][KVSTG]
    __shared__ float mb_s[256];

    int i = blockIdx.x, h = blockIdx.y;
    int t = threadIdx.x;
    int warp = t >> 5, lane = t & 31;
    int gq = lane >> 2, tq = lane & 3;
    int wrow = warp * 32;

    mb_s[t] = 1e9f * (mask[i*NN + t] - 1.0f);

    // stage Q (raw tf32 copy)
    #pragma unroll
    for (int it = 0; it < 8; it++) {
        int idx = t + it*256;
        int row = idx >> 3, c4 = idx & 7;
        cp16(&sbuf[row*36 + c4*4],
             g_q + ((size_t)(i*NN+row))*CZ + h*DH + c4*4);
    }
    CP_COMMIT();
    CP_WAIT0();
    __syncthreads();

    uint32_t qf[2][4][4];
    #pragma unroll
    for (int mi = 0; mi < 2; mi++)
        #pragma unroll
        for (int ks = 0; ks < 4; ks++) {
            int r0 = wrow + mi*16 + gq;
            qf[mi][ks][0] = sbuf[r0*36     + ks*8 + tq];
            qf[mi][ks][1] = sbuf[(r0+8)*36 + ks*8 + tq];
            qf[mi][ks][2] = sbuf[r0*36     + ks*8 + tq + 4];
            qf[mi][ks][3] = sbuf[(r0+8)*36 + ks*8 + tq + 4];
        }
    __syncthreads();   // done reading Q region

    uint32_t* kb[2] = { sbuf,             sbuf + KVSTG };
    uint32_t* vb[2] = { sbuf + 2*KVSTG,   sbuf + 3*KVSTG };

    // stage K/V for jb=0
    #pragma unroll
    for (int it = 0; it < 2; it++) {
        int idx = t + it*256;
        int row = idx >> 3, c4 = idx & 7;
        size_t gb = ((size_t)(i*NN + row))*CZ + h*DH + c4*4;
        cp16(&kb[0][row*36 + c4*4], g_k + gb);
        cp16(&vb[0][row*36 + c4*4], g_v + gb);
    }
    CP_COMMIT();
    CP_WAIT0();
    __syncthreads();

    float mrun[2][2], lrun[2][2];
    float oacc[2][4][4];
    #pragma unroll
    for (int mi = 0; mi < 2; mi++) {
        mrun[mi][0] = mrun[mi][1] = -1e30f;
        lrun[mi][0] = lrun[mi][1] = 0.0f;
        #pragma unroll
        for (int nd = 0; nd < 4; nd++)
            #pragma unroll
            for (int r = 0; r < 4; r++) oacc[mi][nd][r] = 0.0f;
    }

    const float* trib = g_tri + (size_t)h*NPOS;

    for (int jb = 0; jb < 4; jb++) {
        int j0 = jb * 64;
        int cur = jb & 1;
        if (jb < 3) {   // prefetch next K/V block
            int nxt = (jb+1) & 1;
            #pragma unroll
            for (int it = 0; it < 2; it++) {
                int idx = t + it*256;
                int row = idx >> 3, c4 = idx & 7;
                size_t gb = ((size_t)(i*NN + j0 + 64 + row))*CZ + h*DH + c4*4;
                cp16(&kb[nxt][row*36 + c4*4], g_k + gb);
                cp16(&vb[nxt][row*36 + c4*4], g_v + gb);
            }
            CP_COMMIT();
        }
        const uint32_t* k_s = kb[cur];
        const uint32_t* v_s = vb[cur];

        // S = Q K^T
        float sacc[2][8][4];
        #pragma unroll
        for (int mi = 0; mi < 2; mi++)
            #pragma unroll
            for (int ni = 0; ni < 8; ni++)
                #pragma unroll
                for (int r = 0; r < 4; r++) sacc[mi][ni][r] = 0.0f;

        #pragma unroll
        for (int ks = 0; ks < 4; ks++) {
            uint32_t bf[8][2];
            #pragma unroll
            for (int ni = 0; ni < 8; ni++) {
                int base = (ni*8 + gq)*36 + ks*8 + tq;
                bf[ni][0] = k_s[base];
                bf[ni][1] = k_s[base + 4];
            }
            #pragma unroll
            for (int mi = 0; mi < 2; mi++)
                #pragma unroll
                for (int ni = 0; ni < 8; ni++)
                    mma_tf32(sacc[mi][ni], qf[mi][ks], bf[ni]);
        }

        // + mask bias + triangle bias
        #pragma unroll
        for (int mi = 0; mi < 2; mi++) {
            int r0 = wrow + mi*16 + gq;
            #pragma unroll
            for (int ni = 0; ni < 8; ni++) {
                int j = j0 + ni*8 + tq*2;
                float2 t0 = *(const float2*)(trib + (size_t)r0*NN + j);
                float2 t1 = *(const float2*)(trib + (size_t)(r0+8)*NN + j);
                float mb0 = mb_s[j], mb1 = mb_s[j+1];
                sacc[mi][ni][0] += t0.x + mb0;
                sacc[mi][ni][1] += t0.y + mb1;
                sacc[mi][ni][2] += t1.x + mb0;
                sacc[mi][ni][3] += t1.y + mb1;
            }
        }

        // online softmax
        #pragma unroll
        for (int mi = 0; mi < 2; mi++) {
            float mx0 = -1e30f, mx1 = -1e30f;
            #pragma unroll
            for (int ni = 0; ni < 8; ni++) {
                mx0 = fmaxf(mx0, fmaxf(sacc[mi][ni][0], sacc[mi][ni][1]));
                mx1 = fmaxf(mx1, fmaxf(sacc[mi][ni][2], sacc[mi][ni][3]));
            }
            mx0 = fmaxf(mx0, __shfl_xor_sync(0xffffffffu, mx0, 1));
            mx0 = fmaxf(mx0, __shfl_xor_sync(0xffffffffu, mx0, 2));
            mx1 = fmaxf(mx1, __shfl_xor_sync(0xffffffffu, mx1, 1));
            mx1 = fmaxf(mx1, __shfl_xor_sync(0xffffffffu, mx1, 2));
            float mn0 = fmaxf(mrun[mi][0], mx0);
            float mn1 = fmaxf(mrun[mi][1], mx1);
            float f0 = __expf(mrun[mi][0] - mn0);
            float f1 = __expf(mrun[mi][1] - mn1);
            mrun[mi][0] = mn0; mrun[mi][1] = mn1;
            float la0 = lrun[mi][0]*f0, la1 = lrun[mi][1]*f1;
            #pragma unroll
            for (int nd = 0; nd < 4; nd++) {
                oacc[mi][nd][0] *= f0; oacc[mi][nd][1] *= f0;
                oacc[mi][nd][2] *= f1; oacc[mi][nd][3] *= f1;
            }
            #pragma unroll
            for (int ni = 0; ni < 8; ni++) {
                float p0 = __expf(sacc[mi][ni][0] - mn0);
                float p1 = __expf(sacc[mi][ni][1] - mn0);
                float p2 = __expf(sacc[mi][ni][2] - mn1);
                float p3 = __expf(sacc[mi][ni][3] - mn1);
                uint32_t u0 = f2tf32(p0), u1 = f2tf32(p1);
                uint32_t u2 = f2tf32(p2), u3 = f2tf32(p3);
                sacc[mi][ni][0] = __uint_as_float(u0);
                sacc[mi][ni][1] = __uint_as_float(u1);
                sacc[mi][ni][2] = __uint_as_float(u2);
                sacc[mi][ni][3] = __uint_as_float(u3);
                la0 += __uint_as_float(u0) + __uint_as_float(u1);
                la1 += __uint_as_float(u2) + __uint_as_float(u3);
            }
            lrun[mi][0] = la0; lrun[mi][1] = la1;
        }

        // O += P V
        int srcA = (lane & ~3) | (tq >> 1);
        bool odd = (tq & 1);
        #pragma unroll
        for (int ks2 = 0; ks2 < 8; ks2++) {
            uint32_t bf[4][2];
            #pragma unroll
            for (int nd = 0; nd < 4; nd++) {
                bf[nd][0] = v_s[(ks2*8 + tq)*36     + nd*8 + gq];
                bf[nd][1] = v_s[(ks2*8 + tq + 4)*36 + nd*8 + gq];
            }
            #pragma unroll
            for (int mi = 0; mi < 2; mi++) {
                float c0 = sacc[mi][ks2][0], c1 = sacc[mi][ks2][1];
                float c2 = sacc[mi][ks2][2], c3 = sacc[mi][ks2][3];
                float l0a = __shfl_sync(0xffffffffu, c0, srcA);
                float h0a = __shfl_sync(0xffffffffu, c1, srcA);
                float l1a = __shfl_sync(0xffffffffu, c2, srcA);
                float h1a = __shfl_sync(0xffffffffu, c3, srcA);
                float l0b = __shfl_sync(0xffffffffu, c0, srcA+2);
                float h0b = __shfl_sync(0xffffffffu, c1, srcA+2);
                float l1b = __shfl_sync(0xffffffffu, c2, srcA+2);
                float h1b = __shfl_sync(0xffffffffu, c3, srcA+2);
                uint32_t af[4];
                af[0] = __float_as_uint(odd ? h0a : l0a);
                af[1] = __float_as_uint(odd ? h1a : l1a);
                af[2] = __float_as_uint(odd ? h0b : l0b);
                af[3] = __float_as_uint(odd ? h1b : l1b);
                #pragma unroll
                for (int nd = 0; nd < 4; nd++)
                    mma_tf32(oacc[mi][nd], af, bf[nd]);
            }
        }
        if (jb < 3) {
            CP_WAIT0();
            __syncthreads();
        }
    }

    // epilogue: normalize, gate, store tf32
    #pragma unroll
    for (int mi = 0; mi < 2; mi++) {
        float l0 = lrun[mi][0];
        l0 += __shfl_xor_sync(0xffffffffu, l0, 1);
        l0 += __shfl_xor_sync(0xffffffffu, l0, 2);
        float l1 = lrun[mi][1];
        l1 += __shfl_xor_sync(0xffffffffu, l1, 1);
        l1 += __shfl_xor_sync(0xffffffffu, l1, 2);
        float inv0 = 1.0f / l0, inv1 = 1.0f / l1;
        int r0 = wrow + mi*16 + gq;
        #pragma unroll
        for (int nd = 0; nd < 4; nd++) {
            int d = h*DH + nd*8 + tq*2;
            size_t b0 = ((size_t)(i*NN + r0))*CZ + d;
            size_t b1 = ((size_t)(i*NN + r0 + 8))*CZ + d;
            float2 gg0 = *(const float2*)(g_g + b0);
            float2 gg1 = *(const float2*)(g_g + b1);
            *(uint2*)(g_o + b0) = make_uint2(
                f2tf32(oacc[mi][nd][0]*inv0*gg0.x),
                f2tf32(oacc[mi][nd][1]*inv0*gg0.y));
            *(uint2*)(g_o + b1) = make_uint2(
                f2tf32(oacc[mi][nd][2]*inv1*gg1.x),
                f2tf32(oacc[mi][nd][3]*inv1*gg1.y));
        }
    }
}

// ---------------------------------------------------------------------------
extern "C" void kernel_launch(void* const* d_in, const int* in_sizes, int n_in,
                              void* d_out, int out_size)
{
    const float* x     = (const float*)d_in[0];
    const float* mask  = (const float*)d_in[1];
    const float* ln_g  = (const float*)d_in[2];
    const float* ln_b  = (const float*)d_in[3];
    const float* w_tri = (const float*)d_in[4];
    const float* wq    = (const float*)d_in[5];
    const float* wk    = (const float*)d_in[6];
    const float* wv    = (const float*)d_in[7];
    const float* wg    = (const float*)d_in[8];
    const float* bg    = (const float*)d_in[9];
    const float* wo    = (const float*)d_in[10];
    const float* bo    = (const float*)d_in[11];
    float* out = (float*)d_out;

    const int GEMM_SMEM = 4*GSTG*4;   // 73728 B
    cudaFuncSetAttribute(k_proj, cudaFuncAttributeMaxDynamicSharedMemorySize, GEMM_SMEM);
    cudaFuncSetAttribute(k_outp, cudaFuncAttributeMaxDynamicSharedMemorySize, GEMM_SMEM);

    k_prep<<<dim3(64, 5), 256>>>(wq, wk, wv, wg, wo);
    k_ln  <<<NPOS/8, 256>>>(x, ln_g, ln_b, w_tri);
    k_proj<<<dim3(NPOS/128, 4), 256, GEMM_SMEM>>>(bg);
    k_attn<<<dim3(NN, H), 256>>>(mask);
    k_outp<<<NPOS/128, 256, GEMM_SMEM>>>(bo, out);
}

// round 8
// speedup vs baseline: 2.8756x; 1.0569x over previous
#include <cuda_runtime.h>
#include <stdint.h>
#include <math.h>

#define NN   256
#define CZ   128
#define H    4
#define DH   32
#define NPOS (NN*NN)

// Scratch (device globals; device-code access only).
__device__ __align__(16) uint32_t g_xn[NPOS*CZ];
__device__ __align__(16) uint32_t g_q [NPOS*CZ];
__device__ __align__(16) uint32_t g_k [NPOS*CZ];
__device__ __align__(16) uint32_t g_v [NPOS*CZ];
__device__ __align__(16) float    g_g [NPOS*CZ];
__device__ __align__(16) uint32_t g_o [NPOS*CZ];
__device__ __align__(16) float    g_tri[H*NPOS];
__device__ __align__(16) uint32_t g_wt[5*CZ*CZ];   // wq*scale, wk, wv, wg, wo (tf32)

// ---- helpers ---------------------------------------------------------------
__device__ __forceinline__ uint32_t f2tf32(float f) {
    uint32_t u;
    asm("cvt.rna.tf32.f32 %0, %1;" : "=r"(u) : "f"(f));
    return u;
}
__device__ __forceinline__ void mma_tf32(float* d, const uint32_t* a, const uint32_t* b) {
    asm volatile(
        "mma.sync.aligned.m16n8k8.row.col.f32.tf32.tf32.f32 "
        "{%0,%1,%2,%3}, {%4,%5,%6,%7}, {%8,%9}, {%0,%1,%2,%3};"
        : "+f"(d[0]), "+f"(d[1]), "+f"(d[2]), "+f"(d[3])
        : "r"(a[0]), "r"(a[1]), "r"(a[2]), "r"(a[3]),
          "r"(b[0]), "r"(b[1]));
}
__device__ __forceinline__ void cp16(uint32_t* smem_dst, const uint32_t* gsrc) {
    uint32_t sa = (uint32_t)__cvta_generic_to_shared(smem_dst);
    asm volatile("cp.async.ca.shared.global [%0], [%1], 16;"
                 :: "r"(sa), "l"(gsrc) : "memory");
}
#define CP_COMMIT() asm volatile("cp.async.commit_group;" ::: "memory")
#define CP_WAIT0()  asm volatile("cp.async.wait_group 0;" ::: "memory")

// ---------------------------------------------------------------------------
// K0: weight prep — 5 weight matrices to tf32 (wq folded with 1/sqrt(DH))
// ---------------------------------------------------------------------------
__global__ __launch_bounds__(256) void k_prep(
    const float* __restrict__ wq, const float* __restrict__ wk,
    const float* __restrict__ wv, const float* __restrict__ wg,
    const float* __restrict__ wo)
{
    int sel = blockIdx.y;
    int idx = blockIdx.x * 256 + threadIdx.x;
    const float* src = (sel==0) ? wq : (sel==1) ? wk : (sel==2) ? wv
                     : (sel==3) ? wg : wo;
    float v = src[idx];
    if (sel == 0) v *= 0.17677669529663687f;
    g_wt[sel*CZ*CZ + idx] = f2tf32(v);
}

// ---------------------------------------------------------------------------
// K1: LayerNorm (warp per position) + fused triangle bias; xn stored tf32.
// ---------------------------------------------------------------------------
__global__ __launch_bounds__(256) void k_ln(
    const float* __restrict__ x,
    const float* __restrict__ ln_g,
    const float* __restrict__ ln_b,
    const float* __restrict__ w_tri)
{
    int warp = threadIdx.x >> 5;
    int lane = threadIdx.x & 31;
    int pos  = blockIdx.x * 8 + warp;

    float4 v = *(const float4*)(x + (size_t)pos*CZ + lane*4);
    float s  = v.x + v.y + v.z + v.w;
    float ss = v.x*v.x + v.y*v.y + v.z*v.z + v.w*v.w;
    #pragma unroll
    for (int off = 16; off; off >>= 1) {
        s  += __shfl_xor_sync(0xffffffffu, s,  off);
        ss += __shfl_xor_sync(0xffffffffu, ss, off);
    }
    float mu  = s * (1.0f/CZ);
    float var = ss * (1.0f/CZ) - mu*mu;
    float rs  = rsqrtf(var + 1e-5f);

    float4 gg = *(const float4*)(ln_g + lane*4);
    float4 bb = *(const float4*)(ln_b + lane*4);
    float4 y;
    y.x = (v.x - mu)*rs*gg.x + bb.x;
    y.y = (v.y - mu)*rs*gg.y + bb.y;
    y.z = (v.z - mu)*rs*gg.z + bb.z;
    y.w = (v.w - mu)*rs*gg.w + bb.w;
    uint4 u;
    u.x = f2tf32(y.x); u.y = f2tf32(y.y);
    u.z = f2tf32(y.z); u.w = f2tf32(y.w);
    *(uint4*)(g_xn + (size_t)pos*CZ + lane*4) = u;

    #pragma unroll
    for (int h = 0; h < H; h++) {
        float4 w = *(const float4*)(w_tri + h*CZ + lane*4);
        float d = y.x*w.x + y.y*w.y + y.z*w.z + y.w*w.w;
        #pragma unroll
        for (int off = 16; off; off >>= 1)
            d += __shfl_xor_sync(0xffffffffu, d, off);
        if (lane == 0) g_tri[h*NPOS + pos] = d;
    }
}

// ---------------------------------------------------------------------------
// tf32 GEMM 128x128, 8 warps, cp.async double buffer (round-7 verified)
// ---------------------------------------------------------------------------
#define GSTG (128*36)

__device__ __forceinline__ void gemm_stage(
    const uint32_t* __restrict__ A, const uint32_t* __restrict__ W,
    uint32_t* as, uint32_t* ws, int p0, int c0, int t)
{
    #pragma unroll
    for (int i = 0; i < 4; i++) {
        int idx = t + i*256;
        int row = idx >> 3;
        int cs  = idx & 7;
        cp16(as + row*36 + cs*4, A + (size_t)(p0+row)*CZ + c0 + cs*4);
        cp16(ws + row*36 + cs*4, W + (size_t)row*CZ + c0 + cs*4);
    }
}

__device__ __forceinline__ void gemm_tile(
    const uint32_t* __restrict__ A,
    const uint32_t* __restrict__ W,
    float* __restrict__ outf,
    uint32_t* __restrict__ outt,
    const float* __restrict__ bias,
    int act, int p0)
{
    extern __shared__ uint32_t dyn[];
    int t    = threadIdx.x;
    int warp = t >> 5;
    int lane = t & 31;
    int gq   = lane >> 2;
    int tq   = lane & 3;
    int wm   = (warp >> 2) * 64;
    int wn   = (warp & 3) * 32;

    float acc[4][4][4];
    #pragma unroll
    for (int mi = 0; mi < 4; mi++)
        #pragma unroll
        for (int ni = 0; ni < 4; ni++)
            #pragma unroll
            for (int r = 0; r < 4; r++) acc[mi][ni][r] = 0.0f;

    gemm_stage(A, W, dyn, dyn + 2*GSTG, p0, 0, t);
    CP_COMMIT();
    CP_WAIT0();
    __syncthreads();

    for (int c = 0; c < 4; c++) {
        if (c < 3) {
            int nb = (c+1) & 1;
            gemm_stage(A, W, dyn + nb*GSTG, dyn + 2*GSTG + nb*GSTG,
                       p0, (c+1)*32, t);
            CP_COMMIT();
        }
        const uint32_t* as = dyn + (c&1)*GSTG;
        const uint32_t* ws = dyn + 2*GSTG + (c&1)*GSTG;

        #pragma unroll
        for (int ks = 0; ks < 4; ks++) {
            int kb = ks * 8;
            uint32_t afr[4][4], bfr[4][2];
            #pragma unroll
            for (int mi = 0; mi < 4; mi++) {
                int r = wm + mi*16 + gq;
                afr[mi][0] = as[r*36     + kb+tq];
                afr[mi][1] = as[(r+8)*36 + kb+tq];
                afr[mi][2] = as[r*36     + kb+tq+4];
                afr[mi][3] = as[(r+8)*36 + kb+tq+4];
            }
            #pragma unroll
            for (int ni = 0; ni < 4; ni++) {
                int n = wn + ni*8 + gq;
                bfr[ni][0] = ws[n*36 + kb+tq];
                bfr[ni][1] = ws[n*36 + kb+tq+4];
            }
            #pragma unroll
            for (int mi = 0; mi < 4; mi++)
                #pragma unroll
                for (int ni = 0; ni < 4; ni++)
                    mma_tf32(acc[mi][ni], afr[mi], bfr[ni]);
        }
        if (c < 3) {
            CP_WAIT0();
            __syncthreads();
        }
    }

    #pragma unroll
    for (int mi = 0; mi < 4; mi++) {
        #pragma unroll
        for (int ni = 0; ni < 4; ni++) {
            int col = wn + ni*8 + tq*2;
            float b0 = 0.f, b1 = 0.f;
            if (act) { b0 = bias[col]; b1 = bias[col+1]; }
            #pragma unroll
            for (int rr = 0; rr < 2; rr++) {
                int pos = p0 + wm + mi*16 + gq + rr*8;
                float vx = acc[mi][ni][rr*2+0];
                float vy = acc[mi][ni][rr*2+1];
                if (act == 0) {
                    *(uint2*)(outt + (size_t)pos*CZ + col) =
                        make_uint2(f2tf32(vx), f2tf32(vy));
                } else if (act == 1) {
                    vx = 1.0f/(1.0f + __expf(-(vx + b0)));
                    vy = 1.0f/(1.0f + __expf(-(vy + b1)));
                    *(float2*)(outf + (size_t)pos*CZ + col) = make_float2(vx, vy);
                } else {
                    *(float2*)(outf + (size_t)pos*CZ + col) =
                        make_float2(vx + b0, vy + b1);
                }
            }
        }
    }
}

__global__ __launch_bounds__(256, 2) void k_proj(const float* __restrict__ bg)
{
    int sel = blockIdx.y;
    const uint32_t* W = g_wt + (size_t)sel*CZ*CZ;
    uint32_t* outt = (sel==0) ? g_q : (sel==1) ? g_k : (sel==2) ? g_v : nullptr;
    gemm_tile(g_xn, W, g_g, outt, bg, (sel==3) ? 1 : 0, blockIdx.x * 128);
}

__global__ __launch_bounds__(256, 2) void k_outp(
    const float* __restrict__ bo, float* __restrict__ out)
{
    gemm_tile(g_o, g_wt + (size_t)4*CZ*CZ, out, nullptr, bo, 2, blockIdx.x * 128);
}

// ---------------------------------------------------------------------------
// K3: tensor-core attention v2.
// CTA = 128 threads (4 warps x 32 q-rows), grid (NN, 2, H).
// No max-subtraction softmax (logits bounded; masked -> exp(-1e9)=0).
// Q fragments via direct LDG; K/V via cp.async double buffer.
// ---------------------------------------------------------------------------
#define KVSTG (64*36)

__global__ __launch_bounds__(128, 3) void k_attn(const float* __restrict__ mask)
{
    __shared__ uint32_t kvbuf[4*KVSTG];   // K[2] | V[2]
    __shared__ float mb_s[256];

    int i  = blockIdx.x;
    int q0 = blockIdx.y * 128;
    int h  = blockIdx.z;
    int t = threadIdx.x;
    int warp = t >> 5, lane = t & 31;
    int gq = lane >> 2, tq = lane & 3;
    int wrow = q0 + warp * 32;

    mb_s[t]       = 1e9f * (mask[i*NN + t] - 1.0f);
    mb_s[t + 128] = 1e9f * (mask[i*NN + t + 128] - 1.0f);

    uint32_t* kb[2] = { kvbuf,           kvbuf + KVSTG };
    uint32_t* vb[2] = { kvbuf + 2*KVSTG, kvbuf + 3*KVSTG };

    // stage K/V for jb=0
    #pragma unroll
    for (int it = 0; it < 4; it++) {
        int idx = t + it*128;            // 0..511
        int row = idx >> 3, c4 = idx & 7;
        size_t gb = ((size_t)(i*NN + row))*CZ + h*DH + c4*4;
        cp16(&kb[0][row*36 + c4*4], g_k + gb);
        cp16(&vb[0][row*36 + c4*4], g_v + gb);
    }
    CP_COMMIT();

    // Q fragments via direct LDG (scale already folded into wq)
    uint32_t qf[2][4][4];
    #pragma unroll
    for (int mi = 0; mi < 2; mi++) {
        const uint32_t* qr0 = g_q + ((size_t)(i*NN + wrow + mi*16 + gq))*CZ + h*DH;
        const uint32_t* qr8 = qr0 + 8*CZ;
        #pragma unroll
        for (int ks = 0; ks < 4; ks++) {
            qf[mi][ks][0] = qr0[ks*8 + tq];
            qf[mi][ks][1] = qr8[ks*8 + tq];
            qf[mi][ks][2] = qr0[ks*8 + tq + 4];
            qf[mi][ks][3] = qr8[ks*8 + tq + 4];
        }
    }

    float lrun[2][2] = {{0.f,0.f},{0.f,0.f}};
    float oacc[2][4][4];
    #pragma unroll
    for (int mi = 0; mi < 2; mi++)
        #pragma unroll
        for (int nd = 0; nd < 4; nd++)
            #pragma unroll
            for (int r = 0; r < 4; r++) oacc[mi][nd][r] = 0.0f;

    const float* trib = g_tri + (size_t)h*NPOS;

    CP_WAIT0();
    __syncthreads();

    for (int jb = 0; jb < 4; jb++) {
        int j0 = jb * 64;
        int cur = jb & 1;
        if (jb < 3) {
            int nxt = (jb+1) & 1;
            #pragma unroll
            for (int it = 0; it < 4; it++) {
                int idx = t + it*128;
                int row = idx >> 3, c4 = idx & 7;
                size_t gb = ((size_t)(i*NN + j0 + 64 + row))*CZ + h*DH + c4*4;
                cp16(&kb[nxt][row*36 + c4*4], g_k + gb);
                cp16(&vb[nxt][row*36 + c4*4], g_v + gb);
            }
            CP_COMMIT();
        }
        const uint32_t* k_s = kb[cur];
        const uint32_t* v_s = vb[cur];

        // S = Q K^T
        float sacc[2][8][4];
        #pragma unroll
        for (int mi = 0; mi < 2; mi++)
            #pragma unroll
            for (int ni = 0; ni < 8; ni++)
                #pragma unroll
                for (int r = 0; r < 4; r++) sacc[mi][ni][r] = 0.0f;

        #pragma unroll
        for (int ks = 0; ks < 4; ks++) {
            uint32_t bf[8][2];
            #pragma unroll
            for (int ni = 0; ni < 8; ni++) {
                int base = (ni*8 + gq)*36 + ks*8 + tq;
                bf[ni][0] = k_s[base];
                bf[ni][1] = k_s[base + 4];
            }
            #pragma unroll
            for (int mi = 0; mi < 2; mi++)
                #pragma unroll
                for (int ni = 0; ni < 8; ni++)
                    mma_tf32(sacc[mi][ni], qf[mi][ks], bf[ni]);
        }

        // p = exp(S + tri + mask_bias); accumulate l  (no max subtraction)
        #pragma unroll
        for (int mi = 0; mi < 2; mi++) {
            int r0 = wrow + mi*16 + gq;
            float la0 = 0.f, la1 = 0.f;
            #pragma unroll
            for (int ni = 0; ni < 8; ni++) {
                int j = j0 + ni*8 + tq*2;
                float2 t0 = *(const float2*)(trib + (size_t)r0*NN + j);
                float2 t1 = *(const float2*)(trib + (size_t)(r0+8)*NN + j);
                float mb0 = mb_s[j], mb1 = mb_s[j+1];
                float p0 = __expf(sacc[mi][ni][0] + t0.x + mb0);
                float p1 = __expf(sacc[mi][ni][1] + t0.y + mb1);
                float p2 = __expf(sacc[mi][ni][2] + t1.x + mb0);
                float p3 = __expf(sacc[mi][ni][3] + t1.y + mb1);
                uint32_t u0 = f2tf32(p0), u1 = f2tf32(p1);
                uint32_t u2 = f2tf32(p2), u3 = f2tf32(p3);
                sacc[mi][ni][0] = __uint_as_float(u0);
                sacc[mi][ni][1] = __uint_as_float(u1);
                sacc[mi][ni][2] = __uint_as_float(u2);
                sacc[mi][ni][3] = __uint_as_float(u3);
                la0 += __uint_as_float(u0) + __uint_as_float(u1);
                la1 += __uint_as_float(u2) + __uint_as_float(u3);
            }
            lrun[mi][0] += la0; lrun[mi][1] += la1;
        }

        // O += P V
        int srcA = (lane & ~3) | (tq >> 1);
        bool odd = (tq & 1);
        #pragma unroll
        for (int ks2 = 0; ks2 < 8; ks2++) {
            uint32_t bf[4][2];
            #pragma unroll
            for (int nd = 0; nd < 4; nd++) {
                bf[nd][0] = v_s[(ks2*8 + tq)*36     + nd*8 + gq];
                bf[nd][1] = v_s[(ks2*8 + tq + 4)*36 + nd*8 + gq];
            }
            #pragma unroll
            for (int mi = 0; mi < 2; mi++) {
                float c0 = sacc[mi][ks2][0], c1 = sacc[mi][ks2][1];
                float c2 = sacc[mi][ks2][2], c3 = sacc[mi][ks2][3];
                float l0a = __shfl_sync(0xffffffffu, c0, srcA);
                float h0a = __shfl_sync(0xffffffffu, c1, srcA);
                float l1a = __shfl_sync(0xffffffffu, c2, srcA);
                float h1a = __shfl_sync(0xffffffffu, c3, srcA);
                float l0b = __shfl_sync(0xffffffffu, c0, srcA+2);
                float h0b = __shfl_sync(0xffffffffu, c1, srcA+2);
                float l1b = __shfl_sync(0xffffffffu, c2, srcA+2);
                float h1b = __shfl_sync(0xffffffffu, c3, srcA+2);
                uint32_t af[4];
                af[0] = __float_as_uint(odd ? h0a : l0a);
                af[1] = __float_as_uint(odd ? h1a : l1a);
                af[2] = __float_as_uint(odd ? h0b : l0b);
                af[3] = __float_as_uint(odd ? h1b : l1b);
                #pragma unroll
                for (int nd = 0; nd < 4; nd++)
                    mma_tf32(oacc[mi][nd], af, bf[nd]);
            }
        }
        if (jb < 3) {
            CP_WAIT0();
            __syncthreads();
        }
    }

    // epilogue: normalize, gate, store tf32
    #pragma unroll
    for (int mi = 0; mi < 2; mi++) {
        float l0 = lrun[mi][0];
        l0 += __shfl_xor_sync(0xffffffffu, l0, 1);
        l0 += __shfl_xor_sync(0xffffffffu, l0, 2);
        float l1 = lrun[mi][1];
        l1 += __shfl_xor_sync(0xffffffffu, l1, 1);
        l1 += __shfl_xor_sync(0xffffffffu, l1, 2);
        float inv0 = 1.0f / l0, inv1 = 1.0f / l1;
        int r0 = wrow + mi*16 + gq;
        #pragma unroll
        for (int nd = 0; nd < 4; nd++) {
            int d = h*DH + nd*8 + tq*2;
            size_t b0 = ((size_t)(i*NN + r0))*CZ + d;
            size_t b1 = ((size_t)(i*NN + r0 + 8))*CZ + d;
            float2 gg0 = *(const float2*)(g_g + b0);
            float2 gg1 = *(const float2*)(g_g + b1);
            *(uint2*)(g_o + b0) = make_uint2(
                f2tf32(oacc[mi][nd][0]*inv0*gg0.x),
                f2tf32(oacc[mi][nd][1]*inv0*gg0.y));
            *(uint2*)(g_o + b1) = make_uint2(
                f2tf32(oacc[mi][nd][2]*inv1*gg1.x),
                f2tf32(oacc[mi][nd][3]*inv1*gg1.y));
        }
    }
}

// ---------------------------------------------------------------------------
extern "C" void kernel_launch(void* const* d_in, const int* in_sizes, int n_in,
                              void* d_out, int out_size)
{
    const float* x     = (const float*)d_in[0];
    const float* mask  = (const float*)d_in[1];
    const float* ln_g  = (const float*)d_in[2];
    const float* ln_b  = (const float*)d_in[3];
    const float* w_tri = (const float*)d_in[4];
    const float* wq    = (const float*)d_in[5];
    const float* wk    = (const float*)d_in[6];
    const float* wv    = (const float*)d_in[7];
    const float* wg    = (const float*)d_in[8];
    const float* bg    = (const float*)d_in[9];
    const float* wo    = (const float*)d_in[10];
    const float* bo    = (const float*)d_in[11];
    float* out = (float*)d_out;

    const int GEMM_SMEM = 4*GSTG*4;   // 73728 B
    cudaFuncSetAttribute(k_proj, cudaFuncAttributeMaxDynamicSharedMemorySize, GEMM_SMEM);
    cudaFuncSetAttribute(k_outp, cudaFuncAttributeMaxDynamicSharedMemorySize, GEMM_SMEM);

    k_prep<<<dim3(64, 5), 256>>>(wq, wk, wv, wg, wo);
    k_ln  <<<NPOS/8, 256>>>(x, ln_g, ln_b, w_tri);
    k_proj<<<dim3(NPOS/128, 4), 256, GEMM_SMEM>>>(bg);
    k_attn<<<dim3(NN, 2, H), 128>>>(mask);
    k_outp<<<NPOS/128, 256, GEMM_SMEM>>>(bo, out);
}